// round 8
// baseline (speedup 1.0000x reference)
#include <cuda_runtime.h>
#include <math.h>

#define DIM   768
#define D3    2304
#define BATCH 8
#define SLEN  256
#define TLEN  128
#define VOC   50257
#define NHEAD 12
#define HDIM  64

// ---------------- scratch (device globals; no allocation) ----------------
__device__ float g_buf[17301504];          // ~66 MB
__device__ float g_h[2][BATCH * DIM];      // GRU hidden ping-pong
__device__ float g_henc[BATCH * DIM];
__device__ unsigned long long g_best[1024];
__device__ int g_oracle[BATCH];
__device__ double g_part[512];

// g_buf offsets (floats)
#define OFF_SRC_E  0u
#define OFF_DST_E  1572864u
#define OFF_GI     2359296u
#define OFF_FINAL  7077888u
#define OFF_CAND   7864320u
#define OFF_Q      8650752u
#define OFF_KP     10223616u
#define OFF_VP     11010048u
#define OFF_AO     11796480u
#define OFF_COUT   13369344u
#define OFF_CAFT   14942208u
#define OFF_DSTOUT 16515072u

__device__ __forceinline__ float sigm(float x) { return 1.0f / (1.0f + expf(-x)); }

// ---------------- embedding gather + best reset ----------------
__global__ void k_embed(const int* __restrict__ src, const int* __restrict__ dst,
                        const float* __restrict__ wte,
                        float* __restrict__ src_e, float* __restrict__ dst_e) {
    size_t i = (size_t)blockIdx.x * blockDim.x + threadIdx.x;
    if (i < 1024) g_best[i] = 0ull;
    const size_t n1 = (size_t)BATCH * SLEN * DIM;
    if (i < n1) {
        int row = (int)(i / DIM), k = (int)(i % DIM);
        src_e[i] = wte[(size_t)src[row] * DIM + k];
    } else {
        size_t ii = i - n1;
        if (ii < (size_t)BATCH * TLEN * DIM) {
            int row = (int)(ii / DIM), k = (int)(ii % DIM);
            dst_e[ii] = wte[(size_t)dst[row] * DIM + k];
        }
    }
}

// ---------------- NT sgemm: C[m,n] = sum_k A[m,k]*B[n,k] + bias[n] (+resid) ----------
// 128x128x16 tile, 8x8 per thread, 256 threads. M must be a multiple of 128.
// AM=true: fused row-argmax via atomicMax into g_best (C not written).
template <bool AM>
__global__ __launch_bounds__(256) void k_sgemm_nt(
    const float* __restrict__ A, const float* __restrict__ B,
    const float* __restrict__ bias, float* __restrict__ C,
    const float* __restrict__ resid, int M, int N, int K)
{
    __shared__ float As[16][132];
    __shared__ float Bs[16][132];
    int tid = threadIdx.x;
    int tx = tid & 15, ty = tid >> 4;
    int m0 = blockIdx.y * 128, n0 = blockIdx.x * 128;
    int lrow = tid >> 2;
    int lcol = (tid & 3) << 2;

    float acc[8][8];
#pragma unroll
    for (int i = 0; i < 8; ++i)
#pragma unroll
        for (int j = 0; j < 8; ++j) acc[i][j] = 0.f;

    for (int kt = 0; kt < K; kt += 16) {
#pragma unroll
        for (int i = 0; i < 2; ++i) {
            int r = lrow + i * 64;
            float4 v = *(const float4*)(A + (size_t)(m0 + r) * K + kt + lcol);
            As[lcol + 0][r] = v.x; As[lcol + 1][r] = v.y;
            As[lcol + 2][r] = v.z; As[lcol + 3][r] = v.w;
            int n = n0 + r;
            float4 u = make_float4(0.f, 0.f, 0.f, 0.f);
            if (n < N) u = *(const float4*)(B + (size_t)n * K + kt + lcol);
            Bs[lcol + 0][r] = u.x; Bs[lcol + 1][r] = u.y;
            Bs[lcol + 2][r] = u.z; Bs[lcol + 3][r] = u.w;
        }
        __syncthreads();
#pragma unroll
        for (int kk = 0; kk < 16; ++kk) {
            float a[8], b[8];
            *(float4*)&a[0] = *(const float4*)&As[kk][ty * 4];
            *(float4*)&a[4] = *(const float4*)&As[kk][64 + ty * 4];
            *(float4*)&b[0] = *(const float4*)&Bs[kk][tx * 4];
            *(float4*)&b[4] = *(const float4*)&Bs[kk][64 + tx * 4];
#pragma unroll
            for (int i = 0; i < 8; ++i)
#pragma unroll
                for (int j = 0; j < 8; ++j)
                    acc[i][j] = fmaf(a[i], b[j], acc[i][j]);
        }
        __syncthreads();
    }

    int mi[8], nj[8];
#pragma unroll
    for (int i = 0; i < 4; ++i) {
        mi[i] = ty * 4 + i; mi[i + 4] = 64 + ty * 4 + i;
        nj[i] = tx * 4 + i; nj[i + 4] = 64 + tx * 4 + i;
    }

    if (!AM) {
#pragma unroll
        for (int i = 0; i < 8; ++i) {
            size_t m = (size_t)(m0 + mi[i]);
#pragma unroll
            for (int j = 0; j < 8; ++j) {
                int n = n0 + nj[j];
                if (n < N) {
                    float v = acc[i][j] + bias[n];
                    if (resid) v += resid[m * (size_t)N + n];
                    C[m * (size_t)N + n] = v;
                }
            }
        }
    } else {
        __shared__ unsigned long long red[128][17];
#pragma unroll
        for (int i = 0; i < 8; ++i) {
            unsigned long long lb = 0ull;
#pragma unroll
            for (int j = 0; j < 8; ++j) {
                int n = n0 + nj[j];
                if (n < N) {
                    float f = acc[i][j] + bias[n];
                    unsigned u = __float_as_uint(f);
                    unsigned key = (u & 0x80000000u) ? ~u : (u | 0x80000000u);
                    unsigned long long pk =
                        ((unsigned long long)key << 32) |
                        (unsigned long long)(0xFFFFFFFFu - (unsigned)n);
                    if (pk > lb) lb = pk;   // equal value -> smaller n wins
                }
            }
            red[mi[i]][tx] = lb;
        }
        __syncthreads();
        if (tid < 128) {
            unsigned long long bb = 0ull;
#pragma unroll
            for (int x = 0; x < 16; ++x) {
                unsigned long long v = red[tid][x];
                if (v > bb) bb = v;
            }
            atomicMax(&g_best[m0 + tid], bb);
        }
    }
}

// ---------------- per-step GRU with precomputed input gates ----------------
__global__ __launch_bounds__(256) void k_gru_step(
    const float* __restrict__ gi, const float* __restrict__ w_hh,
    const float* __restrict__ b_hh, const int* __restrict__ lens,
    const float* __restrict__ hin, float* __restrict__ hout,
    float* __restrict__ out_seq, int t, int T)
{
    int w = threadIdx.x >> 5, lane = threadIdx.x & 31;
    int j = blockIdx.x * 8 + w;
    const float* wr = w_hh + (size_t)j * DIM;
    const float* wz = w_hh + (size_t)(DIM + j) * DIM;
    const float* wn = w_hh + (size_t)(2 * DIM + j) * DIM;

    float ar[8], az[8], an[8];
#pragma unroll
    for (int b = 0; b < 8; ++b) { ar[b] = 0.f; az[b] = 0.f; an[b] = 0.f; }
    for (int k = lane; k < DIM; k += 32) {
        float w0 = wr[k], w1 = wz[k], w2 = wn[k];
#pragma unroll
        for (int b = 0; b < 8; ++b) {
            float hv = hin[b * DIM + k];
            ar[b] = fmaf(w0, hv, ar[b]);
            az[b] = fmaf(w1, hv, az[b]);
            an[b] = fmaf(w2, hv, an[b]);
        }
    }
#pragma unroll
    for (int b = 0; b < 8; ++b) {
#pragma unroll
        for (int o = 16; o; o >>= 1) {
            ar[b] += __shfl_xor_sync(0xFFFFFFFFu, ar[b], o);
            az[b] += __shfl_xor_sync(0xFFFFFFFFu, az[b], o);
            an[b] += __shfl_xor_sync(0xFFFFFFFFu, an[b], o);
        }
    }
    if (lane < 8) {
        int b = lane;
        const float* gib = gi + (size_t)(b * T + t) * D3;
        float hold = hin[b * DIM + j];
        float r = sigm(gib[j] + ar[b] + b_hh[j]);
        float z = sigm(gib[DIM + j] + az[b] + b_hh[DIM + j]);
        float n = tanhf(gib[2 * DIM + j] + r * (an[b] + b_hh[2 * DIM + j]));
        float hn = (1.f - z) * n + z * hold;
        bool valid = (t < lens[b]);
        hout[b * DIM + j] = valid ? hn : hold;
        if (out_seq) out_seq[(size_t)(b * T + t) * DIM + j] = valid ? hn : 0.f;
    }
}

// ---------------- full GRU cell (input gates computed here) ----------------
__global__ __launch_bounds__(256) void k_gru_cell(
    const float* __restrict__ x_base, const int* __restrict__ xsel, int xstride,
    const float* __restrict__ w_ih, const float* __restrict__ w_hh,
    const float* __restrict__ b_ih, const float* __restrict__ b_hh,
    const float* __restrict__ hin, float* __restrict__ hout,
    float* __restrict__ fout, int tpos)
{
    int w = threadIdx.x >> 5, lane = threadIdx.x & 31;
    int j = blockIdx.x * 8 + w;
    const float* wir = w_ih + (size_t)j * DIM;
    const float* wiz = w_ih + (size_t)(DIM + j) * DIM;
    const float* win = w_ih + (size_t)(2 * DIM + j) * DIM;
    const float* whr = w_hh + (size_t)j * DIM;
    const float* whz = w_hh + (size_t)(DIM + j) * DIM;
    const float* whn = w_hh + (size_t)(2 * DIM + j) * DIM;

    const float* xp[8];
#pragma unroll
    for (int b = 0; b < 8; ++b)
        xp[b] = xsel ? (x_base + (size_t)xsel[b] * DIM)
                     : (x_base + (size_t)b * xstride);

    float ir[8], iz[8], inn[8], hr[8], hz[8], hn[8];
#pragma unroll
    for (int b = 0; b < 8; ++b) { ir[b]=iz[b]=inn[b]=hr[b]=hz[b]=hn[b]=0.f; }
    for (int k = lane; k < DIM; k += 32) {
        float a0 = wir[k], a1 = wiz[k], a2 = win[k];
        float c0 = whr[k], c1 = whz[k], c2 = whn[k];
#pragma unroll
        for (int b = 0; b < 8; ++b) {
            float xv = xp[b][k];
            float hv = hin[b * DIM + k];
            ir[b]  = fmaf(a0, xv, ir[b]);
            iz[b]  = fmaf(a1, xv, iz[b]);
            inn[b] = fmaf(a2, xv, inn[b]);
            hr[b]  = fmaf(c0, hv, hr[b]);
            hz[b]  = fmaf(c1, hv, hz[b]);
            hn[b]  = fmaf(c2, hv, hn[b]);
        }
    }
#pragma unroll
    for (int b = 0; b < 8; ++b) {
#pragma unroll
        for (int o = 16; o; o >>= 1) {
            ir[b]  += __shfl_xor_sync(0xFFFFFFFFu, ir[b], o);
            iz[b]  += __shfl_xor_sync(0xFFFFFFFFu, iz[b], o);
            inn[b] += __shfl_xor_sync(0xFFFFFFFFu, inn[b], o);
            hr[b]  += __shfl_xor_sync(0xFFFFFFFFu, hr[b], o);
            hz[b]  += __shfl_xor_sync(0xFFFFFFFFu, hz[b], o);
            hn[b]  += __shfl_xor_sync(0xFFFFFFFFu, hn[b], o);
        }
    }
    if (lane < 8) {
        int b = lane;
        float hold = hin[b * DIM + j];
        float r = sigm(ir[b] + b_ih[j] + hr[b] + b_hh[j]);
        float z = sigm(iz[b] + b_ih[DIM + j] + hz[b] + b_hh[DIM + j]);
        float n = tanhf(inn[b] + b_ih[2 * DIM + j] + r * (hn[b] + b_hh[2 * DIM + j]));
        float hv = (1.f - z) * n + z * hold;
        hout[b * DIM + j] = hv;
        if (fout) fout[(size_t)(b * TLEN + tpos) * DIM + j] = hv;
    }
}

// ---------------- per-batch argmax of h + gumbel[t] -> g_oracle ----------------
__global__ void k_argmax8(const float* __restrict__ h, const float* __restrict__ g) {
    int w = threadIdx.x >> 5, lane = threadIdx.x & 31;
    if (w >= BATCH) return;
    float bv = -INFINITY; int bi = 0x7FFFFFFF;
    for (int i = lane; i < DIM; i += 32) {
        float v = h[w * DIM + i] + g[w * DIM + i];
        if (v > bv || (v == bv && i < bi)) { bv = v; bi = i; }
    }
#pragma unroll
    for (int o = 16; o; o >>= 1) {
        float ov = __shfl_xor_sync(0xFFFFFFFFu, bv, o);
        int   oi = __shfl_xor_sync(0xFFFFFFFFu, bi, o);
        if (ov > bv || (ov == bv && oi < bi)) { bv = ov; bi = oi; }
    }
    if (lane == 0) g_oracle[w] = bi;
}

// ---------------- misc small kernels ----------------
__global__ void k_zeroh() {
    int i = blockIdx.x * blockDim.x + threadIdx.x;
    if (i < BATCH * DIM) g_h[0][i] = 0.f;
}
__global__ void k_copyhenc() {
    int i = blockIdx.x * blockDim.x + threadIdx.x;
    if (i < BATCH * DIM) g_henc[i] = g_h[0][i];
}
__global__ void k_gather_cand(const float* __restrict__ wte, float* __restrict__ cand) {
    size_t i = (size_t)blockIdx.x * blockDim.x + threadIdx.x;
    if (i < (size_t)1024 * DIM) {
        int m = (int)(i / DIM), k = (int)(i % DIM);
        unsigned id = 0xFFFFFFFFu - (unsigned)(g_best[m] & 0xFFFFFFFFull);
        cand[i] = wte[(size_t)id * DIM + k];
    }
}

// ---------------- attention: one block per (b,h); thread per query s ----------------
__global__ __launch_bounds__(256) void k_attn(
    const float* __restrict__ q, const float* __restrict__ kk,
    const float* __restrict__ vv, const int* __restrict__ dlen,
    float* __restrict__ ao)
{
    __shared__ float Ks[64][65];
    __shared__ float Vs[64][65];
    int b = blockIdx.x / NHEAD, h = blockIdx.x % NHEAD;
    int s = threadIdx.x;
    int len = dlen[b];

    float qv[HDIM];
    const float* qp = q + ((size_t)(b * SLEN + s)) * DIM + h * HDIM;
#pragma unroll
    for (int d = 0; d < HDIM; ++d) qv[d] = qp[d] * 0.125f;   // 1/sqrt(64)

    float m = -INFINITY, l = 0.f;
    float o[HDIM];
#pragma unroll
    for (int d = 0; d < HDIM; ++d) o[d] = 0.f;

    for (int c = 0; c < 2; ++c) {
        for (int i = threadIdx.x; i < 1024; i += 256) {
            int row = i >> 4, c4 = (i & 15) << 2;
            size_t base = ((size_t)(b * TLEN + c * 64 + row)) * DIM + h * HDIM + c4;
            float4 kvv = *(const float4*)(kk + base);
            float4 vvv = *(const float4*)(vv + base);
            Ks[row][c4 + 0] = kvv.x; Ks[row][c4 + 1] = kvv.y;
            Ks[row][c4 + 2] = kvv.z; Ks[row][c4 + 3] = kvv.w;
            Vs[row][c4 + 0] = vvv.x; Vs[row][c4 + 1] = vvv.y;
            Vs[row][c4 + 2] = vvv.z; Vs[row][c4 + 3] = vvv.w;
        }
        __syncthreads();
        for (int tc = 0; tc < 64; ++tc) {
            int t = c * 64 + tc;
            float sc = 0.f;
#pragma unroll
            for (int d = 0; d < HDIM; ++d) sc = fmaf(qv[d], Ks[tc][d], sc);
            if (t >= len) sc = -1e9f;
            float mn = fmaxf(m, sc);
            float scale = expf(m - mn);       // exp(-inf)=0 on first iteration
            float p = expf(sc - mn);
            l = l * scale + p;
#pragma unroll
            for (int d = 0; d < HDIM; ++d)
                o[d] = o[d] * scale + p * Vs[tc][d];
            m = mn;
        }
        __syncthreads();
    }
    float inv = 1.f / l;
    float* op = ao + ((size_t)(b * SLEN + s)) * DIM + h * HDIM;
#pragma unroll
    for (int d = 0; d < HDIM; ++d) op[d] = o[d] * inv;
}

// ---------------- latent loss (deterministic, fixed partition) ----------------
__global__ void k_loss_part(const float* __restrict__ a, const float* __restrict__ b) {
    __shared__ double red[256];
    int blk = blockIdx.x, tid = threadIdx.x;
    size_t base = (size_t)blk * 3072;
    double s = 0.0;
    for (int i = tid; i < 3072; i += 256) {
        double d = (double)a[base + i] - (double)b[base + i];
        s += d * d;
    }
    red[tid] = s;
    __syncthreads();
    for (int o = 128; o; o >>= 1) {
        if (tid < o) red[tid] += red[tid + o];
        __syncthreads();
    }
    if (tid == 0) g_part[blk] = red[0];
}
__global__ void k_loss_final(float* __restrict__ out) {
    if (threadIdx.x == 0) {
        double s = 0.0;
        for (int i = 0; i < 512; ++i) s += g_part[i];
        out[(size_t)1024 * VOC] = (float)s;
    }
}

// ---------------- host driver ----------------
extern "C" void kernel_launch(void* const* d_in, const int* in_sizes, int n_in,
                              void* d_out, int out_size) {
    const int*   src      = (const int*)d_in[0];
    const int*   src_len  = (const int*)d_in[1];
    const int*   dst      = (const int*)d_in[2];
    const int*   dst_len  = (const int*)d_in[3];
    const float* wte      = (const float*)d_in[4];
    const float* e_wih    = (const float*)d_in[5];
    const float* e_whh    = (const float*)d_in[6];
    const float* e_bih    = (const float*)d_in[7];
    const float* e_bhh    = (const float*)d_in[8];
    const float* d_wih    = (const float*)d_in[9];
    const float* d_whh    = (const float*)d_in[10];
    const float* d_bih    = (const float*)d_in[11];
    const float* d_bhh    = (const float*)d_in[12];
    const float* out_w    = (const float*)d_in[13];
    const float* out_b    = (const float*)d_in[14];
    const float* ll_w     = (const float*)d_in[15];
    const float* ll_b     = (const float*)d_in[16];
    const float* a_inw    = (const float*)d_in[17];
    const float* a_inb    = (const float*)d_in[18];
    const float* a_ow     = (const float*)d_in[19];
    const float* a_ob     = (const float*)d_in[20];
    const float* gumbel   = (const float*)d_in[21];
    float* y = (float*)d_out;

    float* gb = nullptr;   cudaGetSymbolAddress((void**)&gb, g_buf);
    float* hbuf0 = nullptr; cudaGetSymbolAddress((void**)&hbuf0, g_h);
    float* henc = nullptr;  cudaGetSymbolAddress((void**)&henc, g_henc);
    int* oracle = nullptr;  cudaGetSymbolAddress((void**)&oracle, g_oracle);
    float* hb[2] = { hbuf0, hbuf0 + BATCH * DIM };

    float* src_e  = gb + OFF_SRC_E;
    float* dst_e  = gb + OFF_DST_E;
    float* gi     = gb + OFF_GI;
    float* finalo = gb + OFF_FINAL;
    float* cand   = gb + OFF_CAND;
    float* qb     = gb + OFF_Q;
    float* kb     = gb + OFF_KP;
    float* vb     = gb + OFF_VP;
    float* aob    = gb + OFF_AO;
    float* coutb  = gb + OFF_COUT;
    float* caftb  = gb + OFF_CAFT;
    float* dstout = gb + OFF_DSTOUT;

    // 1) embeddings + best reset
    k_embed<<<9216, 256>>>(src, dst, wte, src_e, dst_e);

    // 2) encoder scan 1
    k_sgemm_nt<false><<<dim3(18, 16), 256>>>(src_e, e_wih, e_bih, gi, nullptr, 2048, D3, DIM);
    k_zeroh<<<24, 256>>>();
    for (int t = 0; t < SLEN; ++t)
        k_gru_step<<<96, 256>>>(gi, e_whh, e_bhh, src_len,
                                hb[t & 1], hb[(t + 1) & 1], nullptr, t, SLEN);
    k_copyhenc<<<24, 256>>>();

    // 3) scheduled-sampling decode
    k_gru_cell<<<96, 256>>>(dst_e, nullptr, TLEN * DIM,
                            d_wih, d_whh, d_bih, d_bhh, henc, hb[0], finalo, 0);
    for (int t = 0; t < TLEN - 1; ++t) {
        k_argmax8<<<1, 256>>>(hb[t & 1], gumbel + (size_t)t * BATCH * DIM);
        k_gru_cell<<<96, 256>>>(wte, oracle, 0,
                                d_wih, d_whh, d_bih, d_bhh,
                                hb[t & 1], hb[(t + 1) & 1], finalo, t + 1);
    }

    // 4) cand logits + fused argmax; gather cand embeddings
    k_sgemm_nt<true><<<dim3(393, 8), 256>>>(finalo, out_w, out_b, nullptr, nullptr, 1024, VOC, DIM);
    k_gather_cand<<<3072, 256>>>(wte, cand);

    // 5) attention
    k_sgemm_nt<false><<<dim3(6, 16), 256>>>(src_e, a_inw,              a_inb,        qb, nullptr, 2048, DIM, DIM);
    k_sgemm_nt<false><<<dim3(6, 8),  256>>>(cand,  a_inw + 768 * 768,  a_inb + 768,  kb, nullptr, 1024, DIM, DIM);
    k_sgemm_nt<false><<<dim3(6, 8),  256>>>(cand,  a_inw + 1536 * 768, a_inb + 1536, vb, nullptr, 1024, DIM, DIM);
    k_attn<<<96, 256>>>(qb, kb, vb, dst_len, aob);
    k_sgemm_nt<false><<<dim3(6, 16), 256>>>(aob, a_ow, a_ob, coutb, src_e, 2048, DIM, DIM);

    // 6) c_aft + latent loss (c_multi == c_output since PARAM1=0, PARAM2=1)
    k_sgemm_nt<false><<<dim3(6, 16), 256>>>(src_e, ll_w, ll_b, caftb, nullptr, 2048, DIM, DIM);
    k_loss_part<<<512, 256>>>(caftb, coutb);
    k_loss_final<<<1, 32>>>(y);

    // 7) encoder scan 2 on c_output
    k_sgemm_nt<false><<<dim3(18, 16), 256>>>(coutb, e_wih, e_bih, gi, nullptr, 2048, D3, DIM);
    k_zeroh<<<24, 256>>>();
    for (int t = 0; t < SLEN; ++t)
        k_gru_step<<<96, 256>>>(gi, e_whh, e_bhh, src_len,
                                hb[t & 1], hb[(t + 1) & 1], nullptr, t, SLEN);

    // 8) decoder scan (h_enc2 already in hb[0])
    k_sgemm_nt<false><<<dim3(18, 8), 256>>>(dst_e, d_wih, d_bih, gi, nullptr, 1024, D3, DIM);
    for (int t = 0; t < TLEN; ++t)
        k_gru_step<<<96, 256>>>(gi, d_whh, d_bhh, dst_len,
                                hb[t & 1], hb[(t + 1) & 1], dstout, t, TLEN);

    // 9) y = dst_out @ out_w^T + out_b
    k_sgemm_nt<false><<<dim3(393, 8), 256>>>(dstout, out_w, out_b, y, nullptr, 1024, VOC, DIM);
}